// round 10
// baseline (speedup 1.0000x reference)
#include <cuda_runtime.h>
#include <math.h>
#include <stdint.h>

// Problem dims
#define N_PTS   32768            // B*H*W
#define K_CB    2048
#define C_DIM   64
#define B_SZ    32
#define HW      1024             // H*W

// Output offsets (tuple flattened, fp32)
#define OFF_LOSS  ((size_t)0)
#define OFF_STE   ((size_t)1)
#define OFF_PERP  ((size_t)2097153)
#define OFF_OH    ((size_t)2097154)
#define OFF_IDX   ((size_t)69206018)
#define OFF_HIST  ((size_t)69238786)

// Scratch (device globals: sanctioned alternative to cudaMalloc)
__device__ float  g_m[(size_t)N_PTS * K_CB];   // dot(z_n, c_k), 256 MB
__device__ float  g_cc[K_CB];
__device__ float  g_zz[N_PTS];
__device__ int    g_counts[K_CB];
__device__ double g_loss;

__device__ __forceinline__ unsigned long long pack2(float x, float y) {
    unsigned long long r;
    asm("mov.b64 %0, {%1, %2};" : "=l"(r) : "f"(x), "f"(y));
    return r;
}
__device__ __forceinline__ float2 unpack2(unsigned long long v) {
    float2 r;
    asm("mov.b64 {%0, %1}, %2;" : "=f"(r.x), "=f"(r.y) : "l"(v));
    return r;
}

// ---------------------------------------------------------------------------
// K0: row norms (cc, zz) + zero small accumulators.
// Reference is CPU XLA: sum(x*x) is a strictly sequential scalar loop with
// separate mul/add. One thread per row, loop-carried chain — bit-exact.
// ---------------------------------------------------------------------------
__global__ void norms_kernel(const float* __restrict__ z,
                             const float* __restrict__ cb) {
    if (blockIdx.x == 0) {
        for (int i = threadIdx.x; i < K_CB; i += blockDim.x) g_counts[i] = 0;
        if (threadIdx.x == 0) g_loss = 0.0;
    }
    int r = blockIdx.x * blockDim.x + threadIdx.x;
    if (r < K_CB) {
        const float* row = cb + (size_t)r * C_DIM;
        float s = 0.0f;
        #pragma unroll
        for (int c = 0; c < C_DIM; c++) {
            float v = row[c];
            s = __fadd_rn(s, __fmul_rn(v, v));
        }
        g_cc[r] = s;
    } else if (r < K_CB + N_PTS) {
        int n = r - K_CB;
        int b = n >> 10, p = n & 1023;
        const float* zp = z + (size_t)b * (C_DIM * HW) + p;
        float s = 0.0f;
        #pragma unroll
        for (int c = 0; c < C_DIM; c++) {
            float v = zp[(size_t)c * HW];
            s = __fadd_rn(s, __fmul_rn(v, v));
        }
        g_zz[n] = s;
    }
}

// ---------------------------------------------------------------------------
// K1: GEMM  m[n,k] = sum_c z[n,c]*cb[k,c] via packed fma.rn.f32x2 (FFMA2).
// 128x128 tile, 256 threads; each thread: 8 n (as 4 f32x2 pairs) x 8 k.
// Each accumulator lane keeps the sequential c=0..63 FMA chain -> bit-exact
// vs scalar FFMA. k_base selects the k-slice (grid split into 5 launches so
// the harness's ncu -s 5 -c 1 always captures a GEMM slice).
// smem: As[64][128] floats (z as [c][n]); Bs[128][65] ull (cb dup (b,b)).
// ---------------------------------------------------------------------------
#define GEMM_SMEM_BYTES (64 * 128 * 4 + 128 * 65 * 8)   // 99328
__global__ void __launch_bounds__(256) gemm_kernel(const float* __restrict__ z,
                                                   const float* __restrict__ cb,
                                                   int k_base) {
    extern __shared__ unsigned char smem_raw[];
    float* As = (float*)smem_raw;                                    // [c][n] stride 128
    unsigned long long* Bs = (unsigned long long*)(smem_raw + 64 * 128 * 4); // [k][c] stride 65

    int t  = threadIdx.x;
    int n0 = blockIdx.x * 128;
    int k0 = (k_base + blockIdx.y) * 128;
    int b  = n0 >> 10, p0 = n0 & 1023;
    const float* zb = z + (size_t)b * (C_DIM * HW) + p0;

    #pragma unroll
    for (int i = 0; i < 8; i++) {
        int idx = t + i * 256;            // 2048 float4 of As
        int c = idx >> 5, x4 = idx & 31;
        *(float4*)&As[c * 128 + x4 * 4] = *(const float4*)(zb + (size_t)c * HW + x4 * 4);
    }
    #pragma unroll
    for (int i = 0; i < 8; i++) {
        int idx = t + i * 256;            // 2048 float4 of cb -> duplicated pairs
        int kk = idx >> 4, c4 = idx & 15;
        float4 v = *(const float4*)(cb + (size_t)(k0 + kk) * C_DIM + c4 * 4);
        unsigned long long* dst = &Bs[kk * 65 + c4 * 4];
        dst[0] = pack2(v.x, v.x);
        dst[1] = pack2(v.y, v.y);
        dst[2] = pack2(v.z, v.z);
        dst[3] = pack2(v.w, v.w);
    }
    __syncthreads();

    int tn = t & 15, tk = t >> 4;
    unsigned long long acc[4][8];
    #pragma unroll
    for (int i = 0; i < 4; i++)
        #pragma unroll
        for (int j = 0; j < 8; j++) acc[i][j] = 0ULL;

    #pragma unroll
    for (int c = 0; c < 64; c++) {
        ulonglong2 a01 = *(const ulonglong2*)&As[c * 128 + tn * 8];
        ulonglong2 a23 = *(const ulonglong2*)&As[c * 128 + tn * 8 + 4];
        unsigned long long A2[4];
        A2[0] = a01.x; A2[1] = a01.y; A2[2] = a23.x; A2[3] = a23.y;
        #pragma unroll
        for (int j = 0; j < 8; j++) {
            unsigned long long B2 = Bs[(tk * 8 + j) * 65 + c];
            #pragma unroll
            for (int i = 0; i < 4; i++)
                asm("fma.rn.f32x2 %0, %1, %2, %0;"
                    : "+l"(acc[i][j]) : "l"(A2[i]), "l"(B2));
        }
    }

    float* mp = g_m + (size_t)n0 * K_CB + k0;
    #pragma unroll
    for (int i = 0; i < 4; i++) {
        float lo[8], hi[8];
        #pragma unroll
        for (int j = 0; j < 8; j++) {
            float2 u = unpack2(acc[i][j]);
            lo[j] = u.x; hi[j] = u.y;
        }
        float* row0 = mp + (size_t)(tn * 8 + 2 * i) * K_CB + tk * 8;
        float* row1 = row0 + K_CB;
        *(float4*)row0       = *(float4*)&lo[0];
        *(float4*)(row0 + 4) = *(float4*)&lo[4];
        *(float4*)row1       = *(float4*)&hi[0];
        *(float4*)(row1 + 4) = *(float4*)&hi[4];
    }
}

// ---------------------------------------------------------------------------
// K2: per-point pass, WARP-PER-POINT (no block syncs in main loop).
// Block = 64 points (8 warps x 8 iters). Lane owns 16 float4 of the m row
// (k = 4*(lane+32j)+e). Argmin via explicit (value,index) tie-break — order
// independent, identical to jnp.argmin. Distances bit-exact:
// fma(-2,m, fadd(zz,cc)). Softmax weights via __expf + reciprocal (hist only).
// Per-warp hist stored transposed (slot = e*512 + q) for conflict-free STS.
// ---------------------------------------------------------------------------
#define POINT_SMEM_BYTES ((K_CB + 8 * K_CB + 64) * 4)   // 73984
__global__ void __launch_bounds__(256) point_kernel(const float* __restrict__ z,
                                                    const float* __restrict__ cb,
                                                    float* __restrict__ out) {
    extern __shared__ float psmem[];
    float* cc_s   = psmem;                 // [2048] indexed by k
    float* hist_s = psmem + K_CB;          // [8][2048] transposed slots
    int*   idx_s  = (int*)(psmem + K_CB + 8 * K_CB);  // [64]
    __shared__ float s_red[256];

    int t = threadIdx.x, wid = t >> 5, lane = t & 31;
    for (int i = t; i < K_CB; i += 256) cc_s[i] = g_cc[i];
    for (int i = t; i < 8 * K_CB; i += 256) hist_s[i] = 0.0f;
    __syncthreads();

    int n_base = blockIdx.x * 64;
    int b = n_base >> 10;
    float* hw = hist_s + wid * K_CB;

    for (int it = 0; it < 8; it++) {
        int n = n_base + it * 8 + wid;
        float zz = g_zz[n];
        const float4* mrow = (const float4*)(g_m + (size_t)n * K_CB);

        float d[16][4];
        float best = 3.4e38f; int bidx = K_CB;
        #pragma unroll
        for (int j = 0; j < 16; j++) {
            int q = lane + j * 32;
            float4 m4 = mrow[q];
            int k = q * 4;
            float m[4] = {m4.x, m4.y, m4.z, m4.w};
            #pragma unroll
            for (int e = 0; e < 4; e++) {
                float dd = __fmaf_rn(-2.0f, m[e], __fadd_rn(zz, cc_s[k + e]));
                d[j][e] = dd;
                if (dd < best || (dd == best && (k + e) < bidx)) { best = dd; bidx = k + e; }
            }
        }
        #pragma unroll
        for (int o = 16; o > 0; o >>= 1) {
            float v2 = __shfl_xor_sync(0xffffffffu, best, o);
            int   i2 = __shfl_xor_sync(0xffffffffu, bidx, o);
            if (v2 < best || (v2 == best && i2 < bidx)) { best = v2; bidx = i2; }
        }
        // best = dmin, bidx = argmin (all lanes agree)
        float S = 0.0f;
        #pragma unroll
        for (int j = 0; j < 16; j++)
            #pragma unroll
            for (int e = 0; e < 4; e++) {
                float w = __expf(best - d[j][e]);
                d[j][e] = w; S += w;
            }
        #pragma unroll
        for (int o = 16; o > 0; o >>= 1)
            S += __shfl_xor_sync(0xffffffffu, S, o);
        float Sinv = 1.0f / S;
        #pragma unroll
        for (int j = 0; j < 16; j++) {
            int q = lane + j * 32;
            #pragma unroll
            for (int e = 0; e < 4; e++)
                hw[e * 512 + q] += d[j][e] * Sinv;   // stride-1 across lanes
        }

        if (lane == 0) {
            idx_s[it * 8 + wid] = bidx;
            atomicAdd(&g_counts[bidx], 1);
            out[OFF_IDX + n] = (float)bidx;
            out[OFF_OH + ((size_t)b * K_CB + bidx) * HW + (n & 1023)] = 1.0f;
        }
    }
    __syncthreads();

    // flush hist: sum the 8 per-warp copies; slot s -> k = 4*(s&511) + (s>>9)
    for (int s = t; s < K_CB; s += 256) {
        float v = hist_s[s];
        #pragma unroll
        for (int w = 1; w < 8; w++) v += hist_s[w * K_CB + s];
        int k = ((s & 511) << 2) | (s >> 9);
        atomicAdd(&out[OFF_HIST + (size_t)b * K_CB + k], v);
    }

    // ste + loss (coalesced over positions)
    float loss_part = 0.0f;
    int pbase = n_base & 1023;
    for (int e = t; e < 64 * 64; e += 256) {
        int c = e >> 6, pp = e & 63;
        size_t zoff = (size_t)b * (C_DIM * HW) + (size_t)c * HW + pbase + pp;
        float zv = z[zoff];
        float q  = cb[(size_t)idx_s[pp] * C_DIM + c];
        float diff = __fadd_rn(q, -zv);                 // zq - z
        out[OFF_STE + zoff] = __fadd_rn(zv, diff);      // z + (zq - z)
        loss_part = __fmaf_rn(diff, diff, loss_part);
    }
    s_red[t] = loss_part;
    __syncthreads();
    for (int s = 128; s > 0; s >>= 1) {
        if (t < s) s_red[t] += s_red[t + s];
        __syncthreads();
    }
    if (t == 0) atomicAdd(&g_loss, (double)s_red[0]);
}

// ---------------------------------------------------------------------------
// K3: scalars (loss, perplexity)
// ---------------------------------------------------------------------------
__global__ void finalize_kernel(float* __restrict__ out) {
    __shared__ float s_sum[256];
    int t = threadIdx.x;
    float part = 0.0f;
    for (int k = t; k < K_CB; k += 256) {
        float pb = (float)g_counts[k] * (1.0f / 32768.0f);
        part += pb * logf(pb + 1e-10f);
    }
    s_sum[t] = part;
    __syncthreads();
    for (int s = 128; s > 0; s >>= 1) {
        if (t < s) s_sum[t] += s_sum[t + s];
        __syncthreads();
    }
    if (t == 0) {
        out[OFF_PERP] = expf(-s_sum[0]);
        double mean = g_loss / 2097152.0;
        out[OFF_LOSS] = (float)(1.25 * mean);
    }
}

// ---------------------------------------------------------------------------
extern "C" void kernel_launch(void* const* d_in, const int* in_sizes, int n_in,
                              void* d_out, int out_size) {
    const float* z  = (const float*)d_in[0];
    const float* cb = (const float*)d_in[1];
    float* out = (float*)d_out;

    // Aux stream + events for fork/join capture (host objects, created once;
    // no device memory involved).
    static cudaStream_t s_aux = 0;
    static cudaEvent_t  e_fork = 0, e_join = 0;
    if (!s_aux) {
        cudaStreamCreateWithFlags(&s_aux, cudaStreamNonBlocking);
        cudaEventCreateWithFlags(&e_fork, cudaEventDisableTiming);
        cudaEventCreateWithFlags(&e_join, cudaEventDisableTiming);
    }

    // Fork: big onehot memset (268 MB, pure HBM write) overlaps the fma-bound
    // GEMM on the aux stream. Hist memset rides along.
    cudaEventRecord(e_fork, 0);
    cudaStreamWaitEvent(s_aux, e_fork, 0);
    cudaMemsetAsync(out + OFF_OH,   0, (size_t)B_SZ * K_CB * HW * sizeof(float), s_aux);
    cudaMemsetAsync(out + OFF_HIST, 0, (size_t)B_SZ * K_CB * sizeof(float), s_aux);
    cudaEventRecord(e_join, s_aux);

    // norms + zero accumulators (one thread per row, sequential chain)
    {
        int rows = K_CB + N_PTS;
        int blocks = (rows + 255) / 256;
        norms_kernel<<<blocks, 256>>>(z, cb);
    }

    // GEMM (FFMA2), split into 5 k-slices so ncu -s 5 -c 1 captures a slice
    {
        cudaFuncSetAttribute(gemm_kernel, cudaFuncAttributeMaxDynamicSharedMemorySize,
                             GEMM_SMEM_BYTES);
        const int kb[5] = {0, 4, 7, 10, 13};
        const int kn[5] = {4, 3, 3, 3, 3};
        for (int s = 0; s < 5; s++) {
            dim3 grid(N_PTS / 128, kn[s]);
            gemm_kernel<<<grid, 256, GEMM_SMEM_BYTES>>>(z, cb, kb[s]);
        }
    }

    // Join: memsets must be done before point_kernel scatters into onehot/hist
    cudaStreamWaitEvent(0, e_join, 0);

    // per-point pass (warp-per-point)
    {
        cudaFuncSetAttribute(point_kernel, cudaFuncAttributeMaxDynamicSharedMemorySize,
                             POINT_SMEM_BYTES);
        point_kernel<<<N_PTS / 64, 256, POINT_SMEM_BYTES>>>(z, cb, out);
    }

    // scalars
    finalize_kernel<<<1, 256>>>(out);
}

// round 12
// speedup vs baseline: 1.0287x; 1.0287x over previous
#include <cuda_runtime.h>
#include <math.h>
#include <stdint.h>

// Problem dims
#define N_PTS   32768            // B*H*W
#define K_CB    2048
#define C_DIM   64
#define B_SZ    32
#define HW      1024             // H*W

// Output offsets (tuple flattened, fp32)
#define OFF_LOSS  ((size_t)0)
#define OFF_STE   ((size_t)1)
#define OFF_PERP  ((size_t)2097153)
#define OFF_OH    ((size_t)2097154)
#define OFF_IDX   ((size_t)69206018)
#define OFF_HIST  ((size_t)69238786)

// Scratch (device globals: sanctioned alternative to cudaMalloc)
__device__ float  g_m[(size_t)N_PTS * K_CB];   // dot(z_n, c_k), 256 MB
__device__ float  g_cc[K_CB];
__device__ float  g_zz[N_PTS];
__device__ int    g_counts[K_CB];
__device__ double g_loss;

__device__ __forceinline__ unsigned long long pack2(float x, float y) {
    unsigned long long r;
    asm("mov.b64 %0, {%1, %2};" : "=l"(r) : "f"(x), "f"(y));
    return r;
}
__device__ __forceinline__ float2 unpack2(unsigned long long v) {
    float2 r;
    asm("mov.b64 {%0, %1}, %2;" : "=f"(r.x), "=f"(r.y) : "l"(v));
    return r;
}

// ---------------------------------------------------------------------------
// K0: row norms (cc, zz) + zero small accumulators.
// Reference is CPU XLA: sum(x*x) is a strictly sequential scalar loop with
// separate mul/add. One thread per row, loop-carried chain — bit-exact.
// ---------------------------------------------------------------------------
__global__ void norms_kernel(const float* __restrict__ z,
                             const float* __restrict__ cb) {
    if (blockIdx.x == 0) {
        for (int i = threadIdx.x; i < K_CB; i += blockDim.x) g_counts[i] = 0;
        if (threadIdx.x == 0) g_loss = 0.0;
    }
    int r = blockIdx.x * blockDim.x + threadIdx.x;
    if (r < K_CB) {
        const float* row = cb + (size_t)r * C_DIM;
        float s = 0.0f;
        #pragma unroll
        for (int c = 0; c < C_DIM; c++) {
            float v = row[c];
            s = __fadd_rn(s, __fmul_rn(v, v));
        }
        g_cc[r] = s;
    } else if (r < K_CB + N_PTS) {
        int n = r - K_CB;
        int b = n >> 10, p = n & 1023;
        const float* zp = z + (size_t)b * (C_DIM * HW) + p;
        float s = 0.0f;
        #pragma unroll
        for (int c = 0; c < C_DIM; c++) {
            float v = zp[(size_t)c * HW];
            s = __fadd_rn(s, __fmul_rn(v, v));
        }
        g_zz[n] = s;
    }
}

// ---------------------------------------------------------------------------
// K1: GEMM  m[n,k] = sum_c z[n,c]*cb[k,c] via packed fma.rn.f32x2 (FFMA2).
// 128x128 tile, 256 threads; each thread: 8 n (4 f32x2 pairs) x 8 k.
// Each accumulator lane keeps the sequential c=0..63 FMA chain -> bit-exact
// vs scalar FFMA.
// smem: As[64][128] floats (z as [c][n]);
//       Bs[64][130] ull  (cb duplicated (b,b), layout [c][k] so adjacent k
//       pairs load as one LDS.128 full-warp broadcast). Per c-iter per
//       thread: 2 LDS.128 (A) + 4 LDS.128 (B) + 32 FFMA2.
// ---------------------------------------------------------------------------
#define GEMM_SMEM_BYTES (64 * 128 * 4 + 64 * 130 * 8)   // 32768 + 66560 = 99328
__global__ void __launch_bounds__(256) gemm_kernel(const float* __restrict__ z,
                                                   const float* __restrict__ cb) {
    extern __shared__ unsigned char smem_raw[];
    float* As = (float*)smem_raw;                                    // [c][n] stride 128
    unsigned long long* Bs = (unsigned long long*)(smem_raw + 64 * 128 * 4); // [c][k] stride 130

    int t  = threadIdx.x;
    int n0 = blockIdx.x * 128;
    int k0 = blockIdx.y * 128;
    int b  = n0 >> 10, p0 = n0 & 1023;
    const float* zb = z + (size_t)b * (C_DIM * HW) + p0;

    #pragma unroll
    for (int i = 0; i < 8; i++) {
        int idx = t + i * 256;            // 2048 float4 of As
        int c = idx >> 5, x4 = idx & 31;
        *(float4*)&As[c * 128 + x4 * 4] = *(const float4*)(zb + (size_t)c * HW + x4 * 4);
    }
    #pragma unroll
    for (int i = 0; i < 8; i++) {
        int idx = t + i * 256;            // 2048 float4 of cb -> duplicated pairs
        int kk = idx >> 4, c4 = idx & 15; // kk: 0..127, c4: 0..15 (4 c each)
        float4 v = *(const float4*)(cb + (size_t)(k0 + kk) * C_DIM + c4 * 4);
        Bs[(size_t)(c4 * 4 + 0) * 130 + kk] = pack2(v.x, v.x);
        Bs[(size_t)(c4 * 4 + 1) * 130 + kk] = pack2(v.y, v.y);
        Bs[(size_t)(c4 * 4 + 2) * 130 + kk] = pack2(v.z, v.z);
        Bs[(size_t)(c4 * 4 + 3) * 130 + kk] = pack2(v.w, v.w);
    }
    __syncthreads();

    int tn = t & 15, tk = t >> 4;
    unsigned long long acc[4][8];
    #pragma unroll
    for (int i = 0; i < 4; i++)
        #pragma unroll
        for (int j = 0; j < 8; j++) acc[i][j] = 0ULL;

    #pragma unroll
    for (int c = 0; c < 64; c++) {
        ulonglong2 a01 = *(const ulonglong2*)&As[c * 128 + tn * 8];
        ulonglong2 a23 = *(const ulonglong2*)&As[c * 128 + tn * 8 + 4];
        unsigned long long A2[4];
        A2[0] = a01.x; A2[1] = a01.y; A2[2] = a23.x; A2[3] = a23.y;
        #pragma unroll
        for (int j2 = 0; j2 < 4; j2++) {
            ulonglong2 bb = *(const ulonglong2*)&Bs[(size_t)c * 130 + tk * 8 + j2 * 2];
            #pragma unroll
            for (int i = 0; i < 4; i++) {
                asm("fma.rn.f32x2 %0, %1, %2, %0;"
                    : "+l"(acc[i][2 * j2]) : "l"(A2[i]), "l"(bb.x));
                asm("fma.rn.f32x2 %0, %1, %2, %0;"
                    : "+l"(acc[i][2 * j2 + 1]) : "l"(A2[i]), "l"(bb.y));
            }
        }
    }

    float* mp = g_m + (size_t)n0 * K_CB + k0;
    #pragma unroll
    for (int i = 0; i < 4; i++) {
        float lo[8], hi[8];
        #pragma unroll
        for (int j = 0; j < 8; j++) {
            float2 u = unpack2(acc[i][j]);
            lo[j] = u.x; hi[j] = u.y;
        }
        float* row0 = mp + (size_t)(tn * 8 + 2 * i) * K_CB + tk * 8;
        float* row1 = row0 + K_CB;
        *(float4*)row0       = *(float4*)&lo[0];
        *(float4*)(row0 + 4) = *(float4*)&lo[4];
        *(float4*)row1       = *(float4*)&hi[0];
        *(float4*)(row1 + 4) = *(float4*)&hi[4];
    }
}

// ---------------------------------------------------------------------------
// K2: per-point pass, WARP-PER-POINT (no block syncs in main loop).
// Block = 64 points (8 warps x 8 iters). Lane owns 16 float4 of the m row
// (k = 4*(lane+32j)+e). Argmin via explicit (value,index) tie-break — order
// independent, identical to jnp.argmin. Distances bit-exact:
// fma(-2,m, fadd(zz,cc)). Softmax weights via __expf + reciprocal (hist only).
// Per-warp hist stored transposed (slot = e*512 + q) for conflict-free STS.
// ---------------------------------------------------------------------------
#define POINT_SMEM_BYTES ((K_CB + 8 * K_CB + 64) * 4)   // 73984
__global__ void __launch_bounds__(256) point_kernel(const float* __restrict__ z,
                                                    const float* __restrict__ cb,
                                                    float* __restrict__ out) {
    extern __shared__ float psmem[];
    float* cc_s   = psmem;                 // [2048] indexed by k
    float* hist_s = psmem + K_CB;          // [8][2048] transposed slots
    int*   idx_s  = (int*)(psmem + K_CB + 8 * K_CB);  // [64]
    __shared__ float s_red[256];

    int t = threadIdx.x, wid = t >> 5, lane = t & 31;
    for (int i = t; i < K_CB; i += 256) cc_s[i] = g_cc[i];
    for (int i = t; i < 8 * K_CB; i += 256) hist_s[i] = 0.0f;
    __syncthreads();

    int n_base = blockIdx.x * 64;
    int b = n_base >> 10;
    float* hw = hist_s + wid * K_CB;

    for (int it = 0; it < 8; it++) {
        int n = n_base + it * 8 + wid;
        float zz = g_zz[n];
        const float4* mrow = (const float4*)(g_m + (size_t)n * K_CB);

        float d[16][4];
        float best = 3.4e38f; int bidx = K_CB;
        #pragma unroll
        for (int j = 0; j < 16; j++) {
            int q = lane + j * 32;
            float4 m4 = mrow[q];
            int k = q * 4;
            float m[4] = {m4.x, m4.y, m4.z, m4.w};
            #pragma unroll
            for (int e = 0; e < 4; e++) {
                float dd = __fmaf_rn(-2.0f, m[e], __fadd_rn(zz, cc_s[k + e]));
                d[j][e] = dd;
                if (dd < best || (dd == best && (k + e) < bidx)) { best = dd; bidx = k + e; }
            }
        }
        #pragma unroll
        for (int o = 16; o > 0; o >>= 1) {
            float v2 = __shfl_xor_sync(0xffffffffu, best, o);
            int   i2 = __shfl_xor_sync(0xffffffffu, bidx, o);
            if (v2 < best || (v2 == best && i2 < bidx)) { best = v2; bidx = i2; }
        }
        // best = dmin, bidx = argmin (all lanes agree)
        float S = 0.0f;
        #pragma unroll
        for (int j = 0; j < 16; j++)
            #pragma unroll
            for (int e = 0; e < 4; e++) {
                float w = __expf(best - d[j][e]);
                d[j][e] = w; S += w;
            }
        #pragma unroll
        for (int o = 16; o > 0; o >>= 1)
            S += __shfl_xor_sync(0xffffffffu, S, o);
        float Sinv = 1.0f / S;
        #pragma unroll
        for (int j = 0; j < 16; j++) {
            int q = lane + j * 32;
            #pragma unroll
            for (int e = 0; e < 4; e++)
                hw[e * 512 + q] += d[j][e] * Sinv;   // stride-1 across lanes
        }

        if (lane == 0) {
            idx_s[it * 8 + wid] = bidx;
            atomicAdd(&g_counts[bidx], 1);
            out[OFF_IDX + n] = (float)bidx;
            out[OFF_OH + ((size_t)b * K_CB + bidx) * HW + (n & 1023)] = 1.0f;
        }
    }
    __syncthreads();

    // flush hist: sum the 8 per-warp copies; slot s -> k = 4*(s&511) + (s>>9)
    for (int s = t; s < K_CB; s += 256) {
        float v = hist_s[s];
        #pragma unroll
        for (int w = 1; w < 8; w++) v += hist_s[w * K_CB + s];
        int k = ((s & 511) << 2) | (s >> 9);
        atomicAdd(&out[OFF_HIST + (size_t)b * K_CB + k], v);
    }

    // ste + loss (coalesced over positions)
    float loss_part = 0.0f;
    int pbase = n_base & 1023;
    for (int e = t; e < 64 * 64; e += 256) {
        int c = e >> 6, pp = e & 63;
        size_t zoff = (size_t)b * (C_DIM * HW) + (size_t)c * HW + pbase + pp;
        float zv = z[zoff];
        float q  = cb[(size_t)idx_s[pp] * C_DIM + c];
        float diff = __fadd_rn(q, -zv);                 // zq - z
        out[OFF_STE + zoff] = __fadd_rn(zv, diff);      // z + (zq - z)
        loss_part = __fmaf_rn(diff, diff, loss_part);
    }
    s_red[t] = loss_part;
    __syncthreads();
    for (int s = 128; s > 0; s >>= 1) {
        if (t < s) s_red[t] += s_red[t + s];
        __syncthreads();
    }
    if (t == 0) atomicAdd(&g_loss, (double)s_red[0]);
}

// ---------------------------------------------------------------------------
// K3: scalars (loss, perplexity)
// ---------------------------------------------------------------------------
__global__ void finalize_kernel(float* __restrict__ out) {
    __shared__ float s_sum[256];
    int t = threadIdx.x;
    float part = 0.0f;
    for (int k = t; k < K_CB; k += 256) {
        float pb = (float)g_counts[k] * (1.0f / 32768.0f);
        part += pb * logf(pb + 1e-10f);
    }
    s_sum[t] = part;
    __syncthreads();
    for (int s = 128; s > 0; s >>= 1) {
        if (t < s) s_sum[t] += s_sum[t + s];
        __syncthreads();
    }
    if (t == 0) {
        out[OFF_PERP] = expf(-s_sum[0]);
        double mean = g_loss / 2097152.0;
        out[OFF_LOSS] = (float)(1.25 * mean);
    }
}

// ---------------------------------------------------------------------------
extern "C" void kernel_launch(void* const* d_in, const int* in_sizes, int n_in,
                              void* d_out, int out_size) {
    const float* z  = (const float*)d_in[0];
    const float* cb = (const float*)d_in[1];
    float* out = (float*)d_out;

    // Aux stream + events for fork/join capture (host objects, created once;
    // no device memory involved).
    static cudaStream_t s_aux = 0;
    static cudaEvent_t  e_fork = 0, e_join = 0;
    if (!s_aux) {
        cudaStreamCreateWithFlags(&s_aux, cudaStreamNonBlocking);
        cudaEventCreateWithFlags(&e_fork, cudaEventDisableTiming);
        cudaEventCreateWithFlags(&e_join, cudaEventDisableTiming);
    }

    // Fork: big onehot memset (268 MB, pure HBM write) overlaps the fma-bound
    // GEMM on the aux stream. Hist memset rides along.
    cudaEventRecord(e_fork, 0);
    cudaStreamWaitEvent(s_aux, e_fork, 0);
    cudaMemsetAsync(out + OFF_OH,   0, (size_t)B_SZ * K_CB * HW * sizeof(float), s_aux);
    cudaMemsetAsync(out + OFF_HIST, 0, (size_t)B_SZ * K_CB * sizeof(float), s_aux);
    cudaEventRecord(e_join, s_aux);

    // norms + zero accumulators (one thread per row, sequential chain)
    {
        int rows = K_CB + N_PTS;
        int blocks = (rows + 255) / 256;
        norms_kernel<<<blocks, 256>>>(z, cb);
    }

    // GEMM (FFMA2), single launch
    {
        cudaFuncSetAttribute(gemm_kernel, cudaFuncAttributeMaxDynamicSharedMemorySize,
                             GEMM_SMEM_BYTES);
        dim3 grid(N_PTS / 128, K_CB / 128);
        gemm_kernel<<<grid, 256, GEMM_SMEM_BYTES>>>(z, cb);
    }

    // Join: memsets must be done before point_kernel scatters into onehot/hist
    cudaStreamWaitEvent(0, e_join, 0);

    // per-point pass (warp-per-point)
    {
        cudaFuncSetAttribute(point_kernel, cudaFuncAttributeMaxDynamicSharedMemorySize,
                             POINT_SMEM_BYTES);
        point_kernel<<<N_PTS / 64, 256, POINT_SMEM_BYTES>>>(z, cb, out);
    }

    // scalars
    finalize_kernel<<<1, 256>>>(out);
}

// round 14
// speedup vs baseline: 1.1716x; 1.1389x over previous
#include <cuda_runtime.h>
#include <math.h>
#include <stdint.h>

// Problem dims
#define N_PTS   32768            // B*H*W
#define K_CB    2048
#define C_DIM   64
#define B_SZ    32
#define HW      1024             // H*W

// Output offsets (tuple flattened, fp32)
#define OFF_LOSS  ((size_t)0)
#define OFF_STE   ((size_t)1)
#define OFF_PERP  ((size_t)2097153)
#define OFF_OH    ((size_t)2097154)
#define OFF_IDX   ((size_t)69206018)
#define OFF_HIST  ((size_t)69238786)

// Scratch (device globals: sanctioned alternative to cudaMalloc)
__device__ float  g_m[(size_t)N_PTS * K_CB];   // dot(z_n, c_k), 256 MB
__device__ float  g_cc[K_CB];
__device__ float  g_zz[N_PTS];
__device__ int    g_counts[K_CB];
__device__ double g_loss;

__device__ __forceinline__ unsigned long long pack2(float x, float y) {
    unsigned long long r;
    asm("mov.b64 %0, {%1, %2};" : "=l"(r) : "f"(x), "f"(y));
    return r;
}
__device__ __forceinline__ float2 unpack2(unsigned long long v) {
    float2 r;
    asm("mov.b64 {%0, %1}, %2;" : "=f"(r.x), "=f"(r.y) : "l"(v));
    return r;
}

// ---------------------------------------------------------------------------
// K0: row norms (cc, zz) + zero small accumulators.
// Reference is CPU XLA: sum(x*x) is a strictly sequential scalar loop with
// separate mul/add. One thread per row, loop-carried chain — bit-exact.
// ---------------------------------------------------------------------------
__global__ void norms_kernel(const float* __restrict__ z,
                             const float* __restrict__ cb) {
    if (blockIdx.x == 0) {
        for (int i = threadIdx.x; i < K_CB; i += blockDim.x) g_counts[i] = 0;
        if (threadIdx.x == 0) g_loss = 0.0;
    }
    int r = blockIdx.x * blockDim.x + threadIdx.x;
    if (r < K_CB) {
        const float* row = cb + (size_t)r * C_DIM;
        float s = 0.0f;
        #pragma unroll
        for (int c = 0; c < C_DIM; c++) {
            float v = row[c];
            s = __fadd_rn(s, __fmul_rn(v, v));
        }
        g_cc[r] = s;
    } else if (r < K_CB + N_PTS) {
        int n = r - K_CB;
        int b = n >> 10, p = n & 1023;
        const float* zp = z + (size_t)b * (C_DIM * HW) + p;
        float s = 0.0f;
        #pragma unroll
        for (int c = 0; c < C_DIM; c++) {
            float v = zp[(size_t)c * HW];
            s = __fadd_rn(s, __fmul_rn(v, v));
        }
        g_zz[n] = s;
    }
}

// ---------------------------------------------------------------------------
// K1: GEMM  m[n,k] = sum_c z[n,c]*cb[k,c] via packed fma.rn.f32x2 (FFMA2).
// 128x128 tile, 256 threads. Thread (tn=t&15, tk=t>>4) owns
// n in {tn*4..tn*4+3} U {64+tn*4..+3}  (4 f32x2 pairs, conflict-free LDS.128:
// lane addresses are 16B-contiguous) and k = tk*8..tk*8+7.
// B kept in [k][c] duplicated-(b,b) layout (stride 66 ull for 16B alignment);
// inner loop reads 2 c per ulonglong2 -> 8 LDS.128 broadcasts per 2c.
// Each accumulator applies c, c+1, ... sequentially -> bit-exact FMA chain.
// ---------------------------------------------------------------------------
#define GEMM_SMEM_BYTES (64 * 128 * 4 + 128 * 66 * 8)   // 32768 + 67584 = 100352
__global__ void __launch_bounds__(256) gemm_kernel(const float* __restrict__ z,
                                                   const float* __restrict__ cb) {
    extern __shared__ unsigned char smem_raw[];
    float* As = (float*)smem_raw;                                    // [c][n] stride 128
    unsigned long long* Bs = (unsigned long long*)(smem_raw + 64 * 128 * 4); // [k][c] stride 66

    int t  = threadIdx.x;
    int n0 = blockIdx.x * 128;
    int k0 = blockIdx.y * 128;
    int b  = n0 >> 10, p0 = n0 & 1023;
    const float* zb = z + (size_t)b * (C_DIM * HW) + p0;

    #pragma unroll
    for (int i = 0; i < 8; i++) {
        int idx = t + i * 256;            // 2048 float4 of As
        int c = idx >> 5, x4 = idx & 31;
        *(float4*)&As[c * 128 + x4 * 4] = *(const float4*)(zb + (size_t)c * HW + x4 * 4);
    }
    #pragma unroll
    for (int i = 0; i < 8; i++) {
        int idx = t + i * 256;            // 2048 float4 of cb -> duplicated pairs
        int kk = idx >> 4, c4 = idx & 15;
        float4 v = *(const float4*)(cb + (size_t)(k0 + kk) * C_DIM + c4 * 4);
        unsigned long long* dst = &Bs[(size_t)kk * 66 + c4 * 4];
        dst[0] = pack2(v.x, v.x);
        dst[1] = pack2(v.y, v.y);
        dst[2] = pack2(v.z, v.z);
        dst[3] = pack2(v.w, v.w);
    }
    __syncthreads();

    int tn = t & 15, tk = t >> 4;
    unsigned long long acc[4][8];
    #pragma unroll
    for (int i = 0; i < 4; i++)
        #pragma unroll
        for (int j = 0; j < 8; j++) acc[i][j] = 0ULL;

    #pragma unroll
    for (int c = 0; c < 64; c += 2) {
        // A for c and c+1: 16B-contiguous lane addresses -> conflict-free
        ulonglong2 a0  = *(const ulonglong2*)&As[c * 128 + tn * 4];
        ulonglong2 a1  = *(const ulonglong2*)&As[c * 128 + 64 + tn * 4];
        ulonglong2 a0n = *(const ulonglong2*)&As[(c + 1) * 128 + tn * 4];
        ulonglong2 a1n = *(const ulonglong2*)&As[(c + 1) * 128 + 64 + tn * 4];
        unsigned long long Ac[4], Ac1[4];
        Ac[0]  = a0.x;  Ac[1]  = a0.y;  Ac[2]  = a1.x;  Ac[3]  = a1.y;
        Ac1[0] = a0n.x; Ac1[1] = a0n.y; Ac1[2] = a1n.x; Ac1[3] = a1n.y;
        #pragma unroll
        for (int j = 0; j < 8; j++) {
            // (b,b)@c and (b,b)@c+1 in one 16B broadcast load
            ulonglong2 bb = *(const ulonglong2*)&Bs[(size_t)(tk * 8 + j) * 66 + c];
            #pragma unroll
            for (int i = 0; i < 4; i++) {
                asm("fma.rn.f32x2 %0, %1, %2, %0;"
                    : "+l"(acc[i][j]) : "l"(Ac[i]), "l"(bb.x));
                asm("fma.rn.f32x2 %0, %1, %2, %0;"
                    : "+l"(acc[i][j]) : "l"(Ac1[i]), "l"(bb.y));
            }
        }
    }

    // Store: pair i -> rows {tn*4, tn*4+2, 64+tn*4, 64+tn*4+2} (+1 for hi half)
    int nbase[4];
    nbase[0] = tn * 4;       nbase[1] = tn * 4 + 2;
    nbase[2] = 64 + tn * 4;  nbase[3] = 64 + tn * 4 + 2;
    float* mp = g_m + (size_t)n0 * K_CB + k0;
    #pragma unroll
    for (int i = 0; i < 4; i++) {
        float lo[8], hi[8];
        #pragma unroll
        for (int j = 0; j < 8; j++) {
            float2 u = unpack2(acc[i][j]);
            lo[j] = u.x; hi[j] = u.y;
        }
        float* row0 = mp + (size_t)nbase[i] * K_CB + tk * 8;
        float* row1 = row0 + K_CB;
        *(float4*)row0       = *(float4*)&lo[0];
        *(float4*)(row0 + 4) = *(float4*)&lo[4];
        *(float4*)row1       = *(float4*)&hi[0];
        *(float4*)(row1 + 4) = *(float4*)&hi[4];
    }
}

// ---------------------------------------------------------------------------
// K2: per-point pass, WARP-PER-POINT (no block syncs in main loop).
// Block = 64 points (8 warps x 8 iters). Lane owns 16 float4 of the m row
// (k = 4*(lane+32j)+e). Argmin via explicit (value,index) tie-break — order
// independent, identical to jnp.argmin. Distances bit-exact:
// fma(-2,m, fadd(zz,cc)). Softmax weights via __expf + reciprocal (hist only).
// Per-warp hist stored transposed (slot = e*512 + q) for conflict-free STS.
// ---------------------------------------------------------------------------
#define POINT_SMEM_BYTES ((K_CB + 8 * K_CB + 64) * 4)   // 73984
__global__ void __launch_bounds__(256) point_kernel(const float* __restrict__ z,
                                                    const float* __restrict__ cb,
                                                    float* __restrict__ out) {
    extern __shared__ float psmem[];
    float* cc_s   = psmem;                 // [2048] indexed by k
    float* hist_s = psmem + K_CB;          // [8][2048] transposed slots
    int*   idx_s  = (int*)(psmem + K_CB + 8 * K_CB);  // [64]
    __shared__ float s_red[256];

    int t = threadIdx.x, wid = t >> 5, lane = t & 31;
    for (int i = t; i < K_CB; i += 256) cc_s[i] = g_cc[i];
    for (int i = t; i < 8 * K_CB; i += 256) hist_s[i] = 0.0f;
    __syncthreads();

    int n_base = blockIdx.x * 64;
    int b = n_base >> 10;
    float* hw = hist_s + wid * K_CB;

    for (int it = 0; it < 8; it++) {
        int n = n_base + it * 8 + wid;
        float zz = g_zz[n];
        const float4* mrow = (const float4*)(g_m + (size_t)n * K_CB);

        float d[16][4];
        float best = 3.4e38f; int bidx = K_CB;
        #pragma unroll
        for (int j = 0; j < 16; j++) {
            int q = lane + j * 32;
            float4 m4 = mrow[q];
            int k = q * 4;
            float m[4] = {m4.x, m4.y, m4.z, m4.w};
            #pragma unroll
            for (int e = 0; e < 4; e++) {
                float dd = __fmaf_rn(-2.0f, m[e], __fadd_rn(zz, cc_s[k + e]));
                d[j][e] = dd;
                if (dd < best || (dd == best && (k + e) < bidx)) { best = dd; bidx = k + e; }
            }
        }
        #pragma unroll
        for (int o = 16; o > 0; o >>= 1) {
            float v2 = __shfl_xor_sync(0xffffffffu, best, o);
            int   i2 = __shfl_xor_sync(0xffffffffu, bidx, o);
            if (v2 < best || (v2 == best && i2 < bidx)) { best = v2; bidx = i2; }
        }
        // best = dmin, bidx = argmin (all lanes agree)
        float S = 0.0f;
        #pragma unroll
        for (int j = 0; j < 16; j++)
            #pragma unroll
            for (int e = 0; e < 4; e++) {
                float w = __expf(best - d[j][e]);
                d[j][e] = w; S += w;
            }
        #pragma unroll
        for (int o = 16; o > 0; o >>= 1)
            S += __shfl_xor_sync(0xffffffffu, S, o);
        float Sinv = 1.0f / S;
        #pragma unroll
        for (int j = 0; j < 16; j++) {
            int q = lane + j * 32;
            #pragma unroll
            for (int e = 0; e < 4; e++)
                hw[e * 512 + q] += d[j][e] * Sinv;   // stride-1 across lanes
        }

        if (lane == 0) {
            idx_s[it * 8 + wid] = bidx;
            atomicAdd(&g_counts[bidx], 1);
            out[OFF_IDX + n] = (float)bidx;
            out[OFF_OH + ((size_t)b * K_CB + bidx) * HW + (n & 1023)] = 1.0f;
        }
    }
    __syncthreads();

    // flush hist: sum the 8 per-warp copies; slot s -> k = 4*(s&511) + (s>>9)
    for (int s = t; s < K_CB; s += 256) {
        float v = hist_s[s];
        #pragma unroll
        for (int w = 1; w < 8; w++) v += hist_s[w * K_CB + s];
        int k = ((s & 511) << 2) | (s >> 9);
        atomicAdd(&out[OFF_HIST + (size_t)b * K_CB + k], v);
    }

    // ste + loss (coalesced over positions)
    float loss_part = 0.0f;
    int pbase = n_base & 1023;
    for (int e = t; e < 64 * 64; e += 256) {
        int c = e >> 6, pp = e & 63;
        size_t zoff = (size_t)b * (C_DIM * HW) + (size_t)c * HW + pbase + pp;
        float zv = z[zoff];
        float q  = cb[(size_t)idx_s[pp] * C_DIM + c];
        float diff = __fadd_rn(q, -zv);                 // zq - z
        out[OFF_STE + zoff] = __fadd_rn(zv, diff);      // z + (zq - z)
        loss_part = __fmaf_rn(diff, diff, loss_part);
    }
    s_red[t] = loss_part;
    __syncthreads();
    for (int s = 128; s > 0; s >>= 1) {
        if (t < s) s_red[t] += s_red[t + s];
        __syncthreads();
    }
    if (t == 0) atomicAdd(&g_loss, (double)s_red[0]);
}

// ---------------------------------------------------------------------------
// K3: scalars (loss, perplexity)
// ---------------------------------------------------------------------------
__global__ void finalize_kernel(float* __restrict__ out) {
    __shared__ float s_sum[256];
    int t = threadIdx.x;
    float part = 0.0f;
    for (int k = t; k < K_CB; k += 256) {
        float pb = (float)g_counts[k] * (1.0f / 32768.0f);
        part += pb * logf(pb + 1e-10f);
    }
    s_sum[t] = part;
    __syncthreads();
    for (int s = 128; s > 0; s >>= 1) {
        if (t < s) s_sum[t] += s_sum[t + s];
        __syncthreads();
    }
    if (t == 0) {
        out[OFF_PERP] = expf(-s_sum[0]);
        double mean = g_loss / 2097152.0;
        out[OFF_LOSS] = (float)(1.25 * mean);
    }
}

// ---------------------------------------------------------------------------
extern "C" void kernel_launch(void* const* d_in, const int* in_sizes, int n_in,
                              void* d_out, int out_size) {
    const float* z  = (const float*)d_in[0];
    const float* cb = (const float*)d_in[1];
    float* out = (float*)d_out;

    // Aux stream + events for fork/join capture (host objects, created once;
    // no device memory involved).
    static cudaStream_t s_aux = 0;
    static cudaEvent_t  e_fork = 0, e_join = 0;
    if (!s_aux) {
        cudaStreamCreateWithFlags(&s_aux, cudaStreamNonBlocking);
        cudaEventCreateWithFlags(&e_fork, cudaEventDisableTiming);
        cudaEventCreateWithFlags(&e_join, cudaEventDisableTiming);
    }

    // Fork: big onehot memset (268 MB, pure HBM write) overlaps the fma-bound
    // GEMM on the aux stream. Hist memset rides along.
    cudaEventRecord(e_fork, 0);
    cudaStreamWaitEvent(s_aux, e_fork, 0);
    cudaMemsetAsync(out + OFF_OH,   0, (size_t)B_SZ * K_CB * HW * sizeof(float), s_aux);
    cudaMemsetAsync(out + OFF_HIST, 0, (size_t)B_SZ * K_CB * sizeof(float), s_aux);
    cudaEventRecord(e_join, s_aux);

    // norms + zero accumulators (one thread per row, sequential chain)
    {
        int rows = K_CB + N_PTS;
        int blocks = (rows + 255) / 256;
        norms_kernel<<<blocks, 256>>>(z, cb);
    }

    // GEMM (FFMA2), single launch
    {
        cudaFuncSetAttribute(gemm_kernel, cudaFuncAttributeMaxDynamicSharedMemorySize,
                             GEMM_SMEM_BYTES);
        dim3 grid(N_PTS / 128, K_CB / 128);
        gemm_kernel<<<grid, 256, GEMM_SMEM_BYTES>>>(z, cb);
    }

    // Join: memsets must be done before point_kernel scatters into onehot/hist
    cudaStreamWaitEvent(0, e_join, 0);

    // per-point pass (warp-per-point)
    {
        cudaFuncSetAttribute(point_kernel, cudaFuncAttributeMaxDynamicSharedMemorySize,
                             POINT_SMEM_BYTES);
        point_kernel<<<N_PTS / 64, 256, POINT_SMEM_BYTES>>>(z, cb, out);
    }

    // scalars
    finalize_kernel<<<1, 256>>>(out);
}